// round 8
// baseline (speedup 1.0000x reference)
#include <cuda_runtime.h>
#include <cuda_bf16.h>
#include <cstdint>

// ---------------------------------------------------------------------------
// Multi-scale residual VQ (VectorQuantizer2): B=64, C=32, H=W=16, vocab=4096
// scales pn = {1,2,3,4,5,6,8,10,13,16}
//
// One 2-CTA cluster per batch image; codebook split 2048/2048 across the pair.
// Hot loop: codebook register-resident per thread (4 codes x 32 ch as f32x2
// pairs = 128 regs, reloaded per 1024-code chunk), rows streamed with
// broadcast LDS of duplicated {-2z,-2z}; 4 independent fma.rn.f32x2 chains.
// Each f32x2 half reproduces the reference's sequential ascending-c FMA chain
// bit-exactly. Per-row argmin: thread min (ascending code = tie-break), warp
// shfl reduce of packed (dist,idx) u64, per-warp slots merged per chunk, then
// cross-CTA merge via global scratch + barrier.cluster.
// ---------------------------------------------------------------------------

#define NSCALES 10
__device__ __constant__ int c_pns[NSCALES] = {1, 2, 3, 4, 5, 6, 8, 10, 13, 16};

// device scratch (static globals -- no allocation)
__device__ unsigned long long g_epair[32 * 2048]; // [c][pair]={emb[2p][c],emb[2p+1][c]}
__device__ float  g_esq[4096];                    // ||e||^2 (rounded squares, seq sum)
__device__ unsigned long long g_key[64 * 512];    // per-batch, per-rank best keys

// ---------------- shared memory ----------------
struct SMem {
    unsigned long long zdup[256 * 32];  // 64 KB {-2z,-2z} per row/channel; aliases tmpf
    unsigned long long bw8[256 * 8];    // 16 KB per-row per-warp best keys
    unsigned long long bkey[256];       // running best per row
    float frest[8192];                  // [h][w][c]
    float fhat[8192];                   // [h][w][c]
    float zbuf[8192];                   // z rows / gathered codes
    float zsq[256];                     // per-row ||z||^2
    float wu[256];                      // upsample weights [k_in*16 + i_out]
    int   idxs[256];                    // merged final indices
};

__device__ __forceinline__ void cluster_sync_() {
    asm volatile("barrier.cluster.arrive.aligned;\n\t"
                 "barrier.cluster.wait.aligned;\n" ::: "memory");
}

__device__ __forceinline__ void ffma2(unsigned long long& acc,
                                      unsigned long long a, unsigned long long b) {
    asm("fma.rn.f32x2 %0, %1, %2, %0;" : "+l"(acc) : "l"(a), "l"(b));
}
__device__ __forceinline__ unsigned long long pack2(float lo, float hi) {
    unsigned long long d;
    unsigned a = __float_as_uint(lo), b = __float_as_uint(hi);
    asm("mov.b64 %0, {%1, %2};" : "=l"(d) : "r"(a), "r"(b));
    return d;
}
__device__ __forceinline__ void unpack2(unsigned long long v, float& lo, float& hi) {
    unsigned a, b;
    asm("mov.b64 {%0, %1}, %2;" : "=r"(a), "=r"(b) : "l"(v));
    lo = __uint_as_float(a);
    hi = __uint_as_float(b);
}

// jax _fill_keys_cubic_kernel (a = -0.5), each op rounded separately
__device__ __forceinline__ float keys_w(float x) {
    float w;
    if (x < 1.0f) {
        float t = __fmul_rn(1.5f, x);
        t = __fsub_rn(t, 2.5f);
        t = __fmul_rn(t, x);
        t = __fmul_rn(t, x);
        w = __fadd_rn(t, 1.0f);
    } else if (x < 2.0f) {
        float t = __fmul_rn(-0.5f, x);
        t = __fadd_rn(t, 2.5f);
        t = __fmul_rn(t, x);
        t = __fsub_rn(t, 4.0f);
        t = __fmul_rn(t, x);
        w = __fadd_rn(t, 2.0f);
    } else {
        w = 0.0f;
    }
    return w;
}

// ---------------------------------------------------------------------------
// prep: build paired codebook layout + esq
// ---------------------------------------------------------------------------
__global__ void vq_prep_kernel(const float* __restrict__ emb) {
    int p = blockIdx.x * blockDim.x + threadIdx.x;   // pair index 0..2047
    if (p >= 2048) return;
    const float* r0 = emb + (2 * p) * 32;
    const float* r1 = emb + (2 * p + 1) * 32;
    float a0 = 0.0f, a1 = 0.0f;
#pragma unroll
    for (int c = 0; c < 32; c++) {
        float x0 = r0[c], x1 = r1[c];
        a0 = __fadd_rn(a0, __fmul_rn(x0, x0));
        a1 = __fadd_rn(a1, __fmul_rn(x1, x1));
        g_epair[c * 2048 + p] = pack2(x0, x1);
    }
    g_esq[2 * p] = a0;
    g_esq[2 * p + 1] = a1;
}

// ---------------------------------------------------------------------------
// main kernel: one cluster (2 CTAs) per batch image
// ---------------------------------------------------------------------------
extern "C" __global__ void __cluster_dims__(2, 1, 1) __launch_bounds__(256, 1)
vq_main_kernel(const float* __restrict__ f, const float* __restrict__ emb,
               float* __restrict__ out) {
    extern __shared__ char smem_raw[];
    SMem* sm = reinterpret_cast<SMem*>(smem_raw);

    const int tid = threadIdx.x;
    const int lane = tid & 31;
    const int wid = tid >> 5;
    const int b = blockIdx.x >> 1;
    const int rank = blockIdx.x & 1;

    // init: frest = transpose(f) (BCHW -> HWC), fhat = 0
    for (int t = tid; t < 8192; t += 256) {
        int c = t & 31;
        int ij = t >> 5;
        sm->frest[t] = f[(b * 32 + c) * 256 + ij];
        sm->fhat[t] = 0.0f;
    }
    __syncthreads();

    float* tmpf = reinterpret_cast<float*>(sm->zdup);   // scratch alias (26 KB < 64 KB)

    for (int si = 0; si < NSCALES; si++) {
        const int pn = c_pns[si];
        const int N = pn * pn;
        const bool last = (si == NSCALES - 1);

        // ---------- z = area pool of frest (last scale: z aliases frest) ----------
        if (!last) {
            const int n1 = pn * 16 * 32;
            for (int t = tid; t < n1; t += 256) {
                int c = t & 31, w = (t >> 5) & 15, p = t >> 9;
                int sh = (p * 16) / pn;
                int eh = ((p + 1) * 16 + pn - 1) / pn;
                float wt = (float)(1.0 / (double)(eh - sh));
                float acc = 0.0f;
                for (int h = sh; h < eh; h++)
                    acc = fmaf(wt, sm->frest[(h * 16 + w) * 32 + c], acc);
                tmpf[t] = acc;
            }
            __syncthreads();
            const int n2 = N * 32;
            for (int t = tid; t < n2; t += 256) {
                int c = t & 31, q = (t >> 5) % pn, p = (t >> 5) / pn;
                int sw = (q * 16) / pn;
                int ew = ((q + 1) * 16 + pn - 1) / pn;
                float wt = (float)(1.0 / (double)(ew - sw));
                float acc = 0.0f;
                for (int w = sw; w < ew; w++)
                    acc = fmaf(wt, tmpf[p * 512 + w * 32 + c], acc);
                sm->zbuf[t] = acc;
            }
            __syncthreads();
        }
        const float* zp = last ? sm->frest : sm->zbuf;

        // ---------- zsq (rounded squares, sequential ascending sum) ----------
        if (tid < N) {
            float acc = 0.0f;
            for (int c = 0; c < 32; c++) {
                float z = zp[tid * 32 + c];
                acc = __fadd_rn(acc, __fmul_rn(z, z));
            }
            sm->zsq[tid] = acc;
        }
        // build duplicated -2z (overwrites tmpf region -- pool passes done)
        for (int t = tid; t < N * 32; t += 256) {
            float m = __fmul_rn(-2.0f, zp[t]);    // exact *(-2)
            sm->zdup[t] = pack2(m, m);
        }
        for (int t = tid; t < N; t += 256) sm->bkey[t] = 0xFFFFFFFFFFFFFFFFull;
        __syncthreads();

        // ---------- distance + argmin over this CTA's 2048-code half ----------
        for (int chunk = 0; chunk < 2; chunk++) {
            const int cbase = rank * 2048 + chunk * 1024;
            // register-resident codebook: this thread's 4 codes (2 pairs) x 32 ch
            ulonglong2 e2[32];
            const ulonglong2* gep = reinterpret_cast<const ulonglong2*>(g_epair);
            const int pidx = (cbase >> 2) + tid;
#pragma unroll
            for (int c = 0; c < 32; c++) e2[c] = gep[c * 1024 + pidx];
            const float4 eq = *reinterpret_cast<const float4*>(g_esq + cbase + 4 * tid);
            const int cid0 = cbase + 4 * tid;

            for (int r = 0; r < N; r += 2) {
                const int r1v = (r + 1 < N) ? r + 1 : r;
                const float zs0 = sm->zsq[r];
                const float zs1 = sm->zsq[r1v];
                const ulonglong2* z0 =
                    reinterpret_cast<const ulonglong2*>(sm->zdup + r * 32);
                const ulonglong2* z1 =
                    reinterpret_cast<const ulonglong2*>(sm->zdup + r1v * 32);
                unsigned long long a00 = 0ull, a01 = 0ull;  // row r,  pairs 0/1
                unsigned long long a10 = 0ull, a11 = 0ull;  // row r1, pairs 0/1
#pragma unroll
                for (int cc = 0; cc < 16; cc++) {
                    ulonglong2 za = z0[cc];       // channels 2cc, 2cc+1 (row r)
                    ulonglong2 zb = z1[cc];       // channels 2cc, 2cc+1 (row r1)
                    ulonglong2 ea = e2[2 * cc];
                    ulonglong2 eb = e2[2 * cc + 1];
                    ffma2(a00, za.x, ea.x);
                    ffma2(a01, za.x, ea.y);
                    ffma2(a10, zb.x, ea.x);
                    ffma2(a11, zb.x, ea.y);
                    ffma2(a00, za.y, eb.x);
                    ffma2(a01, za.y, eb.y);
                    ffma2(a10, zb.y, eb.x);
                    ffma2(a11, zb.y, eb.y);
                }
                // epilogue row r
                {
                    float h0, h1, h2, h3;
                    unpack2(a00, h0, h1);
                    unpack2(a01, h2, h3);
                    float d0 = __fadd_rn(__fadd_rn(zs0, eq.x), h0);
                    float d1 = __fadd_rn(__fadd_rn(zs0, eq.y), h1);
                    float d2 = __fadd_rn(__fadd_rn(zs0, eq.z), h2);
                    float d3 = __fadd_rn(__fadd_rn(zs0, eq.w), h3);
                    float best = d0;
                    int bi = cid0;
                    if (d1 < best) { best = d1; bi = cid0 + 1; }
                    if (d2 < best) { best = d2; bi = cid0 + 2; }
                    if (d3 < best) { best = d3; bi = cid0 + 3; }
                    unsigned ub = __float_as_uint(best);
                    ub = (ub & 0x80000000u) ? ~ub : (ub ^ 0x80000000u);
                    unsigned long long key =
                        ((unsigned long long)ub << 32) | (unsigned)bi;
#pragma unroll
                    for (int m = 16; m; m >>= 1) {
                        unsigned long long o = __shfl_xor_sync(0xffffffffu, key, m);
                        if (o < key) key = o;
                    }
                    if (lane == 0) sm->bw8[r * 8 + wid] = key;
                }
                // epilogue row r+1
                if (r + 1 < N) {
                    float h0, h1, h2, h3;
                    unpack2(a10, h0, h1);
                    unpack2(a11, h2, h3);
                    float d0 = __fadd_rn(__fadd_rn(zs1, eq.x), h0);
                    float d1 = __fadd_rn(__fadd_rn(zs1, eq.y), h1);
                    float d2 = __fadd_rn(__fadd_rn(zs1, eq.z), h2);
                    float d3 = __fadd_rn(__fadd_rn(zs1, eq.w), h3);
                    float best = d0;
                    int bi = cid0;
                    if (d1 < best) { best = d1; bi = cid0 + 1; }
                    if (d2 < best) { best = d2; bi = cid0 + 2; }
                    if (d3 < best) { best = d3; bi = cid0 + 3; }
                    unsigned ub = __float_as_uint(best);
                    ub = (ub & 0x80000000u) ? ~ub : (ub ^ 0x80000000u);
                    unsigned long long key =
                        ((unsigned long long)ub << 32) | (unsigned)bi;
#pragma unroll
                    for (int m = 16; m; m >>= 1) {
                        unsigned long long o = __shfl_xor_sync(0xffffffffu, key, m);
                        if (o < key) key = o;
                    }
                    if (lane == 0) sm->bw8[(r + 1) * 8 + wid] = key;
                }
            }
            __syncthreads();
            // fold the 8 per-warp keys into bkey
            for (int t = tid; t < N; t += 256) {
                unsigned long long m = sm->bw8[t * 8];
#pragma unroll
                for (int w = 1; w < 8; w++) {
                    unsigned long long o = sm->bw8[t * 8 + w];
                    if (o < m) m = o;
                }
                unsigned long long cur = sm->bkey[t];
                sm->bkey[t] = m < cur ? m : cur;
            }
            __syncthreads();
        }

        // ---------- merge halves across the CTA pair ----------
        for (int t = tid; t < N; t += 256)
            g_key[(b << 9) + (rank << 8) + t] = sm->bkey[t];
        cluster_sync_();   // release/acquire covers gmem at cluster scope
        for (int t = tid; t < N; t += 256) {
            unsigned long long k0 = g_key[(b << 9) + t];
            unsigned long long k1 = g_key[(b << 9) + 256 + t];
            sm->idxs[t] = (int)((k0 < k1 ? k0 : k1) & 0xFFFFFFFFu);
        }
        __syncthreads();

        // ---------- gather h = emb[idx], upsample, update ----------
        if (last) {
            for (int t = tid; t < 8192; t += 256)
                sm->fhat[t] = __fadd_rn(sm->fhat[t],
                                        emb[sm->idxs[t >> 5] * 32 + (t & 31)]);
        } else {
            for (int t = tid; t < N * 32; t += 256)
                sm->zbuf[t] = emb[sm->idxs[t >> 5] * 32 + (t & 31)];
            // weights: compute_weight_mat(pn, 16, 16/pn, 0, keys_cubic, True)
            if (tid < 16) {
                const int i = tid;
                double scl_d = 16.0 / (double)pn;
                float inv = (float)(1.0 / scl_d);
                float sf = __fsub_rn(__fmul_rn(__fadd_rn((float)i, 0.5f), inv), 0.5f);
                float tot = 0.0f;
                for (int k = 0; k < pn; k++) {
                    float x = fabsf(__fsub_rn(sf, (float)k));
                    tot = __fadd_rn(tot, keys_w(x));
                }
                for (int k = 0; k < pn; k++) {
                    float x = fabsf(__fsub_rn(sf, (float)k));
                    sm->wu[k * 16 + i] = __fdiv_rn(keys_w(x), tot);
                }
            }
            __syncthreads();
            // pass 1: contract input-h (k ascending) -> tmpf
            const int n1 = 16 * pn * 32;
            for (int t = tid; t < n1; t += 256) {
                int c = t & 31, kw = (t >> 5) % pn, i = (t >> 5) / pn;
                float acc = 0.0f;
                for (int k = 0; k < pn; k++)
                    acc = fmaf(sm->wu[k * 16 + i], sm->zbuf[(k * pn + kw) * 32 + c], acc);
                tmpf[t] = acc;   // layout (i*pn + kw)*32 + c
            }
            __syncthreads();
            // pass 2: contract input-w, then update fhat/frest
            for (int t = tid; t < 8192; t += 256) {
                int c = t & 31, j = (t >> 5) & 15, i = t >> 9;
                float acc = 0.0f;
                for (int k = 0; k < pn; k++)
                    acc = fmaf(sm->wu[k * 16 + j], tmpf[(i * pn + k) * 32 + c], acc);
                sm->fhat[t] = __fadd_rn(sm->fhat[t], acc);
                sm->frest[t] = __fsub_rn(sm->frest[t], acc);
            }
        }

        cluster_sync_();   // peer done with g_key before next-scale overwrite
        __syncthreads();
    }

    // ---------- write output: BHWC -> BCHW, split channels by rank ----------
    for (int t = tid; t < 4096; t += 256) {
        int c = rank * 16 + (t >> 8);
        int ij = t & 255;
        out[(b * 32 + c) * 256 + ij] = sm->fhat[ij * 32 + c];
    }
}

// ---------------------------------------------------------------------------
extern "C" void kernel_launch(void* const* d_in, const int* in_sizes, int n_in,
                              void* d_out, int out_size) {
    (void)in_sizes; (void)n_in; (void)out_size;
    const float* f = (const float*)d_in[0];     // [64,32,16,16] f32
    const float* emb = (const float*)d_in[1];   // [4096,32] f32
    float* out = (float*)d_out;                 // [64,32,16,16] f32

    static int smem_set = 0;
    if (!smem_set) {
        cudaFuncSetAttribute(vq_main_kernel,
                             cudaFuncAttributeMaxDynamicSharedMemorySize,
                             (int)sizeof(SMem));
        smem_set = 1;
    }

    vq_prep_kernel<<<8, 256>>>(emb);
    vq_main_kernel<<<128, 256, sizeof(SMem)>>>(f, emb, out);
}

// round 9
// speedup vs baseline: 1.0141x; 1.0141x over previous
#include <cuda_runtime.h>
#include <cuda_bf16.h>
#include <cstdint>

// ---------------------------------------------------------------------------
// Multi-scale residual VQ (VectorQuantizer2): B=64, C=32, H=W=16, vocab=4096
// scales pn = {1,2,3,4,5,6,8,10,13,16}
//
// One 2-CTA cluster per batch image; codebook split 2048/2048 across the pair.
// 512 threads/CTA (16 warps/SM) for latency hiding. Each thread holds ONE
// code-pair register-resident ({e_c(2p),e_c(2p+1)} x 32 ch = 64 regs); rows
// streamed 4 at a time with broadcast LDS of pre-duplicated {-2z,-2z}; one
// fma.rn.f32x2 chain per row covers both codes of the pair. Each f32x2 half
// reproduces the reference's sequential ascending-c FMA chain bit-exactly.
// Argmin: thread picks within its pair (lower code on tie), warp reduces via
// redux.sync.min.u32 + ballot (lowest lane = lowest code on tie), 16 per-warp
// slots folded per pass, cross-CTA merge via global scratch + barrier.cluster.
// ---------------------------------------------------------------------------

#define NSCALES 10
__device__ __constant__ int c_pns[NSCALES] = {1, 2, 3, 4, 5, 6, 8, 10, 13, 16};

// device scratch (static globals -- no allocation)
__device__ unsigned long long g_epair[32 * 2048]; // [c][pair]={emb[2p][c],emb[2p+1][c]}
__device__ float  g_esq[4096];                    // ||e||^2 (rounded squares, seq sum)
__device__ unsigned long long g_key[64 * 512];    // per-batch, per-rank best keys

// ---------------- shared memory ----------------
struct SMem {
    unsigned long long zdup[256 * 32];  // 64 KB {-2z,-2z} per row/channel; aliases tmpf
    unsigned long long bw[256 * 16];    // 32 KB per-row per-warp best keys
    unsigned long long bkey[256];       // running best per row
    float frest[8192];                  // [h][w][c]
    float fhat[8192];                   // [h][w][c]
    float zbuf[8192];                   // z rows / gathered codes
    float zsq[256];                     // per-row ||z||^2
    float wu[256];                      // upsample weights [k_in*16 + i_out]
    int   idxs[256];                    // merged final indices
};

__device__ __forceinline__ void cluster_sync_() {
    asm volatile("barrier.cluster.arrive.aligned;\n\t"
                 "barrier.cluster.wait.aligned;\n" ::: "memory");
}

__device__ __forceinline__ void ffma2(unsigned long long& acc,
                                      unsigned long long a, unsigned long long b) {
    asm("fma.rn.f32x2 %0, %1, %2, %0;" : "+l"(acc) : "l"(a), "l"(b));
}
__device__ __forceinline__ unsigned long long pack2(float lo, float hi) {
    unsigned long long d;
    unsigned a = __float_as_uint(lo), b = __float_as_uint(hi);
    asm("mov.b64 %0, {%1, %2};" : "=l"(d) : "r"(a), "r"(b));
    return d;
}
__device__ __forceinline__ void unpack2(unsigned long long v, float& lo, float& hi) {
    unsigned a, b;
    asm("mov.b64 {%0, %1}, %2;" : "=r"(a), "=r"(b) : "l"(v));
    lo = __uint_as_float(a);
    hi = __uint_as_float(b);
}
__device__ __forceinline__ unsigned redux_min_u32(unsigned v) {
    unsigned r;
    asm("redux.sync.min.u32 %0, %1, 0xffffffff;" : "=r"(r) : "r"(v));
    return r;
}

// jax _fill_keys_cubic_kernel (a = -0.5), each op rounded separately
__device__ __forceinline__ float keys_w(float x) {
    float w;
    if (x < 1.0f) {
        float t = __fmul_rn(1.5f, x);
        t = __fsub_rn(t, 2.5f);
        t = __fmul_rn(t, x);
        t = __fmul_rn(t, x);
        w = __fadd_rn(t, 1.0f);
    } else if (x < 2.0f) {
        float t = __fmul_rn(-0.5f, x);
        t = __fadd_rn(t, 2.5f);
        t = __fmul_rn(t, x);
        t = __fsub_rn(t, 4.0f);
        t = __fmul_rn(t, x);
        w = __fadd_rn(t, 2.0f);
    } else {
        w = 0.0f;
    }
    return w;
}

// ---------------------------------------------------------------------------
// prep: build paired codebook layout + esq
// ---------------------------------------------------------------------------
__global__ void vq_prep_kernel(const float* __restrict__ emb) {
    int p = blockIdx.x * blockDim.x + threadIdx.x;   // pair index 0..2047
    if (p >= 2048) return;
    const float* r0 = emb + (2 * p) * 32;
    const float* r1 = emb + (2 * p + 1) * 32;
    float a0 = 0.0f, a1 = 0.0f;
#pragma unroll
    for (int c = 0; c < 32; c++) {
        float x0 = r0[c], x1 = r1[c];
        a0 = __fadd_rn(a0, __fmul_rn(x0, x0));
        a1 = __fadd_rn(a1, __fmul_rn(x1, x1));
        g_epair[c * 2048 + p] = pack2(x0, x1);
    }
    g_esq[2 * p] = a0;
    g_esq[2 * p + 1] = a1;
}

// ---------------------------------------------------------------------------
// main kernel: one cluster (2 CTAs) per batch image, 512 threads
// ---------------------------------------------------------------------------
extern "C" __global__ void __cluster_dims__(2, 1, 1) __launch_bounds__(512, 1)
vq_main_kernel(const float* __restrict__ f, const float* __restrict__ emb,
               float* __restrict__ out) {
    extern __shared__ char smem_raw[];
    SMem* sm = reinterpret_cast<SMem*>(smem_raw);

    const int tid = threadIdx.x;
    const int lane = tid & 31;
    const int wid = tid >> 5;
    const int b = blockIdx.x >> 1;
    const int rank = blockIdx.x & 1;

    // init: frest = transpose(f) (BCHW -> HWC), fhat = 0
    for (int t = tid; t < 8192; t += 512) {
        int c = t & 31;
        int ij = t >> 5;
        sm->frest[t] = f[(b * 32 + c) * 256 + ij];
        sm->fhat[t] = 0.0f;
    }
    __syncthreads();

    float* tmpf = reinterpret_cast<float*>(sm->zdup);   // scratch alias (<= 26 KB use)

    for (int si = 0; si < NSCALES; si++) {
        const int pn = c_pns[si];
        const int N = pn * pn;
        const bool last = (si == NSCALES - 1);

        // ---------- z = area pool of frest (last scale: z aliases frest) ----------
        if (!last) {
            const int n1 = pn * 16 * 32;
            for (int t = tid; t < n1; t += 512) {
                int c = t & 31, w = (t >> 5) & 15, p = t >> 9;
                int sh = (p * 16) / pn;
                int eh = ((p + 1) * 16 + pn - 1) / pn;
                float wt = (float)(1.0 / (double)(eh - sh));
                float acc = 0.0f;
                for (int h = sh; h < eh; h++)
                    acc = fmaf(wt, sm->frest[(h * 16 + w) * 32 + c], acc);
                tmpf[t] = acc;
            }
            __syncthreads();
            const int n2 = N * 32;
            for (int t = tid; t < n2; t += 512) {
                int c = t & 31, q = (t >> 5) % pn, p = (t >> 5) / pn;
                int sw = (q * 16) / pn;
                int ew = ((q + 1) * 16 + pn - 1) / pn;
                float wt = (float)(1.0 / (double)(ew - sw));
                float acc = 0.0f;
                for (int w = sw; w < ew; w++)
                    acc = fmaf(wt, tmpf[p * 512 + w * 32 + c], acc);
                sm->zbuf[t] = acc;
            }
            __syncthreads();
        }
        const float* zp = last ? sm->frest : sm->zbuf;

        // ---------- zsq (rounded squares, sequential ascending sum) ----------
        if (tid < N) {
            float acc = 0.0f;
            for (int c = 0; c < 32; c++) {
                float z = zp[tid * 32 + c];
                acc = __fadd_rn(acc, __fmul_rn(z, z));
            }
            sm->zsq[tid] = acc;
        }
        // build duplicated -2z (overwrites tmpf region -- pool passes done)
        for (int t = tid; t < N * 32; t += 512) {
            float m = __fmul_rn(-2.0f, zp[t]);    // exact *(-2)
            sm->zdup[t] = pack2(m, m);
        }
        for (int t = tid; t < N; t += 512) sm->bkey[t] = 0xFFFFFFFFFFFFFFFFull;
        __syncthreads();

        // ---------- distance + argmin over this CTA's 2048-code half ----------
        for (int pass = 0; pass < 2; pass++) {
            const int pidx = rank * 1024 + pass * 512 + tid;   // global pair idx
            unsigned long long e2[32];
#pragma unroll
            for (int c = 0; c < 32; c++) e2[c] = g_epair[c * 2048 + pidx];
            const float2 eq = *reinterpret_cast<const float2*>(g_esq + 2 * pidx);
            const int cid0 = 2 * pidx;

            for (int r = 0; r < N; r += 4) {
                int rv[4];
#pragma unroll
                for (int i = 0; i < 4; i++) {
                    int q = r + i;
                    rv[i] = q < N ? q : N - 1;
                }
                const ulonglong2* zz0 =
                    reinterpret_cast<const ulonglong2*>(sm->zdup + rv[0] * 32);
                const ulonglong2* zz1 =
                    reinterpret_cast<const ulonglong2*>(sm->zdup + rv[1] * 32);
                const ulonglong2* zz2 =
                    reinterpret_cast<const ulonglong2*>(sm->zdup + rv[2] * 32);
                const ulonglong2* zz3 =
                    reinterpret_cast<const ulonglong2*>(sm->zdup + rv[3] * 32);
                unsigned long long a0 = 0ull, a1 = 0ull, a2 = 0ull, a3 = 0ull;
#pragma unroll
                for (int cc = 0; cc < 16; cc++) {
                    ulonglong2 zA = zz0[cc];   // {-2z[2cc]}x2, {-2z[2cc+1]}x2
                    ulonglong2 zB = zz1[cc];
                    ulonglong2 zC = zz2[cc];
                    ulonglong2 zD = zz3[cc];
                    unsigned long long ea = e2[2 * cc];
                    unsigned long long eb = e2[2 * cc + 1];
                    ffma2(a0, zA.x, ea);
                    ffma2(a1, zB.x, ea);
                    ffma2(a2, zC.x, ea);
                    ffma2(a3, zD.x, ea);
                    ffma2(a0, zA.y, eb);
                    ffma2(a1, zB.y, eb);
                    ffma2(a2, zC.y, eb);
                    ffma2(a3, zD.y, eb);
                }
                unsigned long long accs[4] = {a0, a1, a2, a3};
#pragma unroll
                for (int i = 0; i < 4; i++) {
                    if (r + i < N) {
                        float lo, hi;
                        unpack2(accs[i], lo, hi);
                        float zs = sm->zsq[rv[i]];
                        float d0 = __fadd_rn(__fadd_rn(zs, eq.x), lo);
                        float d1 = __fadd_rn(__fadd_rn(zs, eq.y), hi);
                        float best = d0;
                        int bi = cid0;
                        if (d1 < best) { best = d1; bi = cid0 + 1; }
                        unsigned ub = __float_as_uint(best);
                        ub = (ub & 0x80000000u) ? ~ub : (ub ^ 0x80000000u);
                        unsigned mn = redux_min_u32(ub);
                        unsigned msk = __ballot_sync(0xffffffffu, ub == mn);
                        if (lane == (__ffs(msk) - 1))
                            sm->bw[rv[i] * 16 + wid] =
                                ((unsigned long long)ub << 32) | (unsigned)bi;
                    }
                }
            }
            __syncthreads();
            // fold the 16 per-warp keys into bkey
            for (int t = tid; t < N; t += 512) {
                unsigned long long m = sm->bw[t * 16];
#pragma unroll
                for (int w = 1; w < 16; w++) {
                    unsigned long long o = sm->bw[t * 16 + w];
                    if (o < m) m = o;
                }
                unsigned long long cur = sm->bkey[t];
                sm->bkey[t] = m < cur ? m : cur;
            }
            __syncthreads();
        }

        // ---------- merge halves across the CTA pair ----------
        for (int t = tid; t < N; t += 512)
            g_key[(b << 9) + (rank << 8) + t] = sm->bkey[t];
        cluster_sync_();   // release/acquire covers gmem at cluster scope
        for (int t = tid; t < N; t += 512) {
            unsigned long long k0 = g_key[(b << 9) + t];
            unsigned long long k1 = g_key[(b << 9) + 256 + t];
            sm->idxs[t] = (int)((k0 < k1 ? k0 : k1) & 0xFFFFFFFFu);
        }
        __syncthreads();

        // ---------- gather h = emb[idx], upsample, update ----------
        if (last) {
            for (int t = tid; t < 8192; t += 512)
                sm->fhat[t] = __fadd_rn(sm->fhat[t],
                                        emb[sm->idxs[t >> 5] * 32 + (t & 31)]);
        } else {
            for (int t = tid; t < N * 32; t += 512)
                sm->zbuf[t] = emb[sm->idxs[t >> 5] * 32 + (t & 31)];
            // weights: compute_weight_mat(pn, 16, 16/pn, 0, keys_cubic, True)
            if (tid < 16) {
                const int i = tid;
                double scl_d = 16.0 / (double)pn;
                float inv = (float)(1.0 / scl_d);
                float sf = __fsub_rn(__fmul_rn(__fadd_rn((float)i, 0.5f), inv), 0.5f);
                float tot = 0.0f;
                for (int k = 0; k < pn; k++) {
                    float x = fabsf(__fsub_rn(sf, (float)k));
                    tot = __fadd_rn(tot, keys_w(x));
                }
                for (int k = 0; k < pn; k++) {
                    float x = fabsf(__fsub_rn(sf, (float)k));
                    sm->wu[k * 16 + i] = __fdiv_rn(keys_w(x), tot);
                }
            }
            __syncthreads();
            // pass 1: contract input-h (k ascending) -> tmpf
            const int n1 = 16 * pn * 32;
            for (int t = tid; t < n1; t += 512) {
                int c = t & 31, kw = (t >> 5) % pn, i = (t >> 5) / pn;
                float acc = 0.0f;
                for (int k = 0; k < pn; k++)
                    acc = fmaf(sm->wu[k * 16 + i], sm->zbuf[(k * pn + kw) * 32 + c], acc);
                tmpf[t] = acc;   // layout (i*pn + kw)*32 + c
            }
            __syncthreads();
            // pass 2: contract input-w, then update fhat/frest
            for (int t = tid; t < 8192; t += 512) {
                int c = t & 31, j = (t >> 5) & 15, i = t >> 9;
                float acc = 0.0f;
                for (int k = 0; k < pn; k++)
                    acc = fmaf(sm->wu[k * 16 + j], tmpf[(i * pn + k) * 32 + c], acc);
                sm->fhat[t] = __fadd_rn(sm->fhat[t], acc);
                sm->frest[t] = __fsub_rn(sm->frest[t], acc);
            }
        }

        cluster_sync_();   // peer done with g_key before next-scale overwrite
        __syncthreads();
    }

    // ---------- write output: BHWC -> BCHW ----------
    for (int t = tid; t < 4096; t += 512) {
        int c = rank * 16 + (t >> 8);
        int ij = t & 255;
        out[(b * 32 + c) * 256 + ij] = sm->fhat[ij * 32 + c];
    }
}

// ---------------------------------------------------------------------------
extern "C" void kernel_launch(void* const* d_in, const int* in_sizes, int n_in,
                              void* d_out, int out_size) {
    (void)in_sizes; (void)n_in; (void)out_size;
    const float* f = (const float*)d_in[0];     // [64,32,16,16] f32
    const float* emb = (const float*)d_in[1];   // [4096,32] f32
    float* out = (float*)d_out;                 // [64,32,16,16] f32

    static int smem_set = 0;
    if (!smem_set) {
        cudaFuncSetAttribute(vq_main_kernel,
                             cudaFuncAttributeMaxDynamicSharedMemorySize,
                             (int)sizeof(SMem));
        smem_set = 1;
    }

    vq_prep_kernel<<<8, 256>>>(emb);
    vq_main_kernel<<<128, 512, sizeof(SMem)>>>(f, emb, out);
}